// round 3
// baseline (speedup 1.0000x reference)
#include <cuda_runtime.h>
#include <math.h>

// Problem constants
// input [256,1024] f32, W_xy [2304,1024] f32, b_xy [2304], w_out [5], b_out [1]
// out [256,256] f32
#define M_DIM 256
#define N_DIM 2304
#define K_DIM 1024
#define NN 256      // 2^OUT_BITS
#define COPIES 4

// GEMM tiling
#define BM 64
#define BN 64
#define BK 16
#define PAD 68   // row stride in floats for shared tiles (16B-aligned: 68*4=272)

// Scratch for xy = input @ W^T + b   (256*2304 floats = 2.36 MB)
__device__ float g_xy[M_DIM * N_DIM];

// ---------------- packed f32x2 helpers (sm_100+ FFMA2 path) ----------------
__device__ __forceinline__ void fma2(unsigned long long& c,
                                     unsigned long long a,
                                     unsigned long long b) {
    asm("fma.rn.f32x2 %0, %1, %2, %0;" : "+l"(c) : "l"(a), "l"(b));
}
__device__ __forceinline__ unsigned long long dup2(float x) {
    unsigned long long r;
    asm("mov.b64 %0, {%1, %1};" : "=l"(r) : "f"(x));
    return r;
}
__device__ __forceinline__ float lo2(unsigned long long v) {
    return __int_as_float((int)(unsigned int)(v & 0xffffffffull));
}
__device__ __forceinline__ float hi2(unsigned long long v) {
    return __int_as_float((int)(unsigned int)(v >> 32));
}

// ---------------- Kernel 1: fp32 GEMM  xy[m,n] = sum_k A[m,k]*W[n,k] + b[n] ----
// Grid: (N_DIM/BN, M_DIM/BM) = (36, 4) = 144 blocks (~1 wave on 148 SMs)
// 256 threads, each computes a 4x4 micro-tile using FFMA2 (2 outputs/op).
__global__ __launch_bounds__(256) void gemm_kernel(
    const float* __restrict__ A,     // [256,1024]
    const float* __restrict__ W,     // [2304,1024]
    const float* __restrict__ bias)  // [2304]
{
    __shared__ float As[2][BK][PAD];
    __shared__ float Ws[2][BK][PAD];

    const int tid = threadIdx.x;
    const int row = tid >> 2;          // 0..63 : tile row loaded by this thread
    const int kk4 = (tid & 3) << 2;    // 0,4,8,12 : k offset (float4)
    const int tx  = tid & 15;          // 0..15 : output col group
    const int ty  = tid >> 4;          // 0..15 : output row group
    const int m0  = blockIdx.y * BM;
    const int n0  = blockIdx.x * BN;

    const float* Aload = A + (size_t)(m0 + row) * K_DIM + kk4;
    const float* Wload = W + (size_t)(n0 + row) * K_DIM + kk4;

    unsigned long long acc[4][2];
#pragma unroll
    for (int r = 0; r < 4; ++r) { acc[r][0] = 0ull; acc[r][1] = 0ull; }

    // prologue: load + store tile 0
    {
        float4 ra = *(const float4*)Aload;
        float4 rw = *(const float4*)Wload;
        As[0][kk4 + 0][row] = ra.x; As[0][kk4 + 1][row] = ra.y;
        As[0][kk4 + 2][row] = ra.z; As[0][kk4 + 3][row] = ra.w;
        Ws[0][kk4 + 0][row] = rw.x; Ws[0][kk4 + 1][row] = rw.y;
        Ws[0][kk4 + 2][row] = rw.z; Ws[0][kk4 + 3][row] = rw.w;
    }
    __syncthreads();

    const int KT = K_DIM / BK;  // 64
    for (int t = 0; t < KT; ++t) {
        const int cur = t & 1;
        float4 na, nw;
        if (t < KT - 1) {
            na = *(const float4*)(Aload + (t + 1) * BK);
            nw = *(const float4*)(Wload + (t + 1) * BK);
        }
#pragma unroll
        for (int kk = 0; kk < BK; ++kk) {
            float4 a = *(const float4*)&As[cur][kk][ty << 2];
            ulonglong2 b = *(const ulonglong2*)&Ws[cur][kk][tx << 2];
            unsigned long long d0 = dup2(a.x), d1 = dup2(a.y);
            unsigned long long d2 = dup2(a.z), d3 = dup2(a.w);
            fma2(acc[0][0], d0, b.x); fma2(acc[0][1], d0, b.y);
            fma2(acc[1][0], d1, b.x); fma2(acc[1][1], d1, b.y);
            fma2(acc[2][0], d2, b.x); fma2(acc[2][1], d2, b.y);
            fma2(acc[3][0], d3, b.x); fma2(acc[3][1], d3, b.y);
        }
        if (t < KT - 1) {
            const int nb = cur ^ 1;
            As[nb][kk4 + 0][row] = na.x; As[nb][kk4 + 1][row] = na.y;
            As[nb][kk4 + 2][row] = na.z; As[nb][kk4 + 3][row] = na.w;
            Ws[nb][kk4 + 0][row] = nw.x; Ws[nb][kk4 + 1][row] = nw.y;
            Ws[nb][kk4 + 2][row] = nw.z; Ws[nb][kk4 + 3][row] = nw.w;
        }
        __syncthreads();
    }

    // epilogue: unpack + bias + store
    const int gm = m0 + (ty << 2);
    const int gn = n0 + (tx << 2);
    float4 bb = *(const float4*)&bias[gn];
#pragma unroll
    for (int r = 0; r < 4; ++r) {
        float4 v;
        v.x = lo2(acc[r][0]) + bb.x;
        v.y = hi2(acc[r][0]) + bb.y;
        v.z = lo2(acc[r][1]) + bb.z;
        v.w = hi2(acc[r][1]) + bb.w;
        *(float4*)&g_xy[(size_t)(gm + r) * N_DIM + gn] = v;
    }
}

// ---------------- Kernel 2: fused soft-XOR + 1x1 conv ----------------
// One block per batch element. Thread j owns output column j for all 4 copies.
// Copies are packed as float4 per position so each i-step is:
//   1 broadcast LDS.128 (Ex) + 1 XOR-permuted LDS.128 (Ey, conflict-free) + 2 FFMA2
__global__ __launch_bounds__(256) void softxor_kernel(
    const float* __restrict__ w_out,  // [5]
    const float* __restrict__ b_out,  // [1]
    float* __restrict__ out)          // [256,256]
{
    __shared__ float4 ex[NN];
    __shared__ float4 ey[NN];

    const int b = blockIdx.x;
    const int j = threadIdx.x;
    const float* row = g_xy + (size_t)b * N_DIM;

    float4 e, f;
    e.x = expf(row[0 * NN + j]);
    e.y = expf(row[1 * NN + j]);
    e.z = expf(row[2 * NN + j]);
    e.w = expf(row[3 * NN + j]);
    f.x = expf(row[4 * NN + j]);
    f.y = expf(row[5 * NN + j]);
    f.z = expf(row[6 * NN + j]);
    f.w = expf(row[7 * NN + j]);
    ex[j] = e;
    ey[j] = f;
    const float skip = row[8 * NN + j];
    __syncthreads();

    unsigned long long a01 = 0ull, a23 = 0ull, c01 = 0ull, c23 = 0ull;
#pragma unroll 4
    for (int i = 0; i < NN; i += 2) {
        ulonglong2 e0 = *(const ulonglong2*)(ex + i);
        ulonglong2 f0 = *(const ulonglong2*)(ey + (i ^ j));
        fma2(a01, e0.x, f0.x);
        fma2(a23, e0.y, f0.y);
        ulonglong2 e1 = *(const ulonglong2*)(ex + i + 1);
        ulonglong2 f1 = *(const ulonglong2*)(ey + ((i + 1) ^ j));
        fma2(c01, e1.x, f1.x);
        fma2(c23, e1.y, f1.y);
    }
    float s0 = lo2(a01) + lo2(c01);
    float s1 = hi2(a01) + hi2(c01);
    float s2 = lo2(a23) + lo2(c23);
    float s3 = hi2(a23) + hi2(c23);

    const float w0 = w_out[0], w1 = w_out[1], w2 = w_out[2], w3 = w_out[3],
                w4 = w_out[4];
    float r = w0 * logf(s0) + w1 * logf(s1) + w2 * logf(s2) + w3 * logf(s3)
            + w4 * skip + b_out[0];
    out[(size_t)b * NN + j] = r;
}

// ---------------- launch ----------------
extern "C" void kernel_launch(void* const* d_in, const int* in_sizes, int n_in,
                              void* d_out, int out_size) {
    const float* inp  = (const float*)d_in[0];   // input  [256,1024]
    const float* W    = (const float*)d_in[1];   // W_xy   [2304,1024]
    const float* bxy  = (const float*)d_in[2];   // b_xy   [2304]
    const float* wout = (const float*)d_in[3];   // w_out  [5]
    const float* bout = (const float*)d_in[4];   // b_out  [1]
    float* out = (float*)d_out;                  // [256,256]

    dim3 grid(N_DIM / BN, M_DIM / BM);  // (36, 4)
    gemm_kernel<<<grid, 256>>>(inp, W, bxy);
    softxor_kernel<<<M_DIM, NN>>>(wout, bout, out);
}